// round 3
// baseline (speedup 1.0000x reference)
#include <cuda_runtime.h>
#include <stdint.h>

#define BB 8
#define NN 4096
#define DD 1024
#define HH 1024
#define NQ 64
#define TOPK 1024
#define SCALE_INV 0.03125f   // 1/sqrt(1024)

// ---------------- scratch (static device globals; no allocs allowed) ----------
__device__ float g_Qp_part[8 * NQ * DD];      // split-k partials for Qp
__device__ float g_Qp[NQ * DD];               // query_embed @ key_w^T   [q][d]
__device__ float g_qb[NQ];                    // query_embed @ key_b
__device__ float g_db[BB * NN];               // density bias per token
__device__ float g_S[BB * NQ * NN];           // attention scores [b][q][n]
__device__ float g_L[BB * NQ];                // logsumexp per (b,q) row
__device__ float g_t[BB * NN];                // max_q (s - L)  (monotone importance)
__device__ int   g_sel[BB * TOPK];            // selected indices, ascending
__device__ float g_C1;                        // sum_{b1==0, w1>0} w1*w2
__device__ int   g_m;                         // # irregular (b1 != 0) terms
__device__ int   g_irr[2048];                 // irregular term indices

// ---------------- f32x2 helpers ----------------------------------------------
__device__ __forceinline__ unsigned long long pack2(float a, float b) {
    unsigned long long r;
    asm("mov.b64 %0, {%1,%2};" : "=l"(r) : "f"(a), "f"(b));
    return r;
}
__device__ __forceinline__ unsigned long long fma2(unsigned long long a,
                                                   unsigned long long b,
                                                   unsigned long long c) {
    unsigned long long d;
    asm("fma.rn.f32x2 %0, %1, %2, %3;" : "=l"(d) : "l"(a), "l"(b), "l"(c));
    return d;
}
__device__ __forceinline__ void unpack2(unsigned long long v, float& lo, float& hi) {
    asm("mov.b64 {%0,%1}, %2;" : "=f"(lo), "=f"(hi) : "l"(v));
}

// ---------------- K1a: Qp split-k partials ------------------------------------
// grid (64 d-tiles of 16, 8 k-splits of 128), block 256
__global__ void k_qp_part(const float* __restrict__ qe, const float* __restrict__ kw) {
    __shared__ float qe_s[64 * 129];
    __shared__ float kw_s[16 * 129];
    int t = threadIdx.x;
    int d0 = blockIdx.x * 16;
    int k0 = blockIdx.y * 128;
    #pragma unroll
    for (int i = 0; i < 32; i++) {
        int idx = t + i * 256;
        int q = idx >> 7, k = idx & 127;
        qe_s[q * 129 + k] = qe[q * HH + k0 + k];
    }
    #pragma unroll
    for (int i = 0; i < 8; i++) {
        int idx = t + i * 256;
        int d = idx >> 7, k = idx & 127;
        kw_s[d * 129 + k] = kw[(size_t)(d0 + d) * HH + k0 + k];
    }
    __syncthreads();
    int tq = t & 63, tg = t >> 6;
    float acc[4] = {0.f, 0.f, 0.f, 0.f};
    for (int k = 0; k < 128; k++) {
        float qv = qe_s[tq * 129 + k];
        #pragma unroll
        for (int i = 0; i < 4; i++)
            acc[i] = fmaf(qv, kw_s[(tg * 4 + i) * 129 + k], acc[i]);
    }
    #pragma unroll
    for (int i = 0; i < 4; i++)
        g_Qp_part[(size_t)blockIdx.y * (NQ * DD) + tq * DD + d0 + tg * 4 + i] = acc[i];
}

// ---------------- K1b: reduce split-k ----------------------------------------
__global__ void k_qp_reduce() {
    int idx = blockIdx.x * 256 + threadIdx.x;   // 65536 total
    float s = 0.f;
    #pragma unroll
    for (int j = 0; j < 8; j++) s += g_Qp_part[(size_t)j * (NQ * DD) + idx];
    g_Qp[idx] = s;
}

// ---------------- K1c: qb = qe @ key_b ----------------------------------------
__global__ void k_qb(const float* __restrict__ qe, const float* __restrict__ kb) {
    __shared__ float red[128];
    int q = blockIdx.x, t = threadIdx.x;
    float s = 0.f;
    for (int h = t; h < HH; h += 128) s += qe[q * HH + h] * kb[h];
    red[t] = s; __syncthreads();
    for (int o = 64; o > 0; o >>= 1) {
        if (t < o) red[t] += red[t + o];
        __syncthreads();
    }
    if (t == 0) g_qb[q] = red[0];
}

// ---------------- K2a: density prep (analytic collapse of the 2048-wide MLP) --
// relu(d*w1 + b1)*w2 with b1==0 and d>=0 reduces to d*w1*w2 for w1>0.
// Terms with b1 != 0 go to an exact "irregular" list (empty for this problem).
__global__ void k_prep(const float* __restrict__ w1, const float* __restrict__ b1,
                       const float* __restrict__ w2) {
    int lane = threadIdx.x;  // 32 threads
    float c = 0.f;
    int m = 0;
    for (int base = 0; base < 2048; base += 32) {
        int j = base + lane;
        float a = w1[j], bb = b1[j];
        unsigned mask = __ballot_sync(0xffffffffu, bb != 0.f);
        if (bb != 0.f) {
            int pos = m + __popc(mask & ((1u << lane) - 1u));
            g_irr[pos] = j;
        } else if (a > 0.f) {
            c += a * w2[j];
        }
        m += __popc(mask);
    }
    #pragma unroll
    for (int o = 16; o > 0; o >>= 1) c += __shfl_down_sync(0xffffffffu, c, o);
    if (lane == 0) { g_C1 = c; g_m = m; }
}

// ---------------- K2b: density bias apply -------------------------------------
__global__ void k_density(const float* __restrict__ dens,
                          const float* __restrict__ w1, const float* __restrict__ b1,
                          const float* __restrict__ w2, const float* __restrict__ b2) {
    int idx = blockIdx.x * 256 + threadIdx.x;   // < 32768
    float d = dens[idx];
    float acc = fmaf(d, g_C1, b2[0]);
    int m = g_m;
    for (int i = 0; i < m; i++) {
        int j = g_irr[i];
        acc += fmaxf(fmaf(d, w1[j], b1[j]), 0.f) * w2[j];
    }
    g_db[idx] = acc;
}

// ---------------- K3: scores GEMM  S[b,q,n] -----------------------------------
// grid (32 n-tiles of 128, 8 b) = 256 blocks, block 256, 2 CTAs/SM -> one wave.
// Thread tile 8q x 4n via f32x2; k-chunk 32.
#define TFS 132
#define BK  32
__global__ __launch_bounds__(256, 2) void k_scores(const float* __restrict__ tf) {
    __shared__ __align__(16) float tf_s[BK * TFS];   // [kk][n], padded rows
    __shared__ __align__(16) float qp_s[BK * 64];    // [kk][q]
    int t = threadIdx.x;
    int n0 = blockIdx.x * 128;
    int b  = blockIdx.y;
    int qg = t >> 5, lane = t & 31;
    const float* tfb = tf + (size_t)b * NN * DD;

    unsigned long long acc[8][2];
    #pragma unroll
    for (int i = 0; i < 8; i++) { acc[i][0] = 0ull; acc[i][1] = 0ull; }

    for (int k0 = 0; k0 < DD; k0 += BK) {
        // tf chunk: 128 rows x 32 k -> k-major smem (1024 float4, 4 per thread)
        #pragma unroll
        for (int r = 0; r < 4; r++) {
            int f = t + r * 256;
            int n = f >> 3, kq = (f & 7) * 4;
            float4 v = *(const float4*)(tfb + (size_t)(n0 + n) * DD + k0 + kq);
            tf_s[(kq + 0) * TFS + n] = v.x;
            tf_s[(kq + 1) * TFS + n] = v.y;
            tf_s[(kq + 2) * TFS + n] = v.z;
            tf_s[(kq + 3) * TFS + n] = v.w;
        }
        // Qp chunk: 64 rows x 32 k -> k-major smem (512 float4, 2 per thread)
        #pragma unroll
        for (int r = 0; r < 2; r++) {
            int f = t + r * 256;
            int q = f >> 3, kq = (f & 7) * 4;
            float4 v = *(const float4*)(g_Qp + (size_t)q * DD + k0 + kq);
            qp_s[(kq + 0) * 64 + q] = v.x;
            qp_s[(kq + 1) * 64 + q] = v.y;
            qp_s[(kq + 2) * 64 + q] = v.z;
            qp_s[(kq + 3) * 64 + q] = v.w;
        }
        __syncthreads();
        #pragma unroll
        for (int kk = 0; kk < BK; kk++) {
            float4 tv = *(const float4*)&tf_s[kk * TFS + lane * 4];
            unsigned long long t01 = pack2(tv.x, tv.y);
            unsigned long long t23 = pack2(tv.z, tv.w);
            float4 qa = *(const float4*)&qp_s[kk * 64 + qg * 8];
            float4 qc = *(const float4*)&qp_s[kk * 64 + qg * 8 + 4];
            float qv[8] = {qa.x, qa.y, qa.z, qa.w, qc.x, qc.y, qc.z, qc.w};
            #pragma unroll
            for (int i = 0; i < 8; i++) {
                unsigned long long qd = pack2(qv[i], qv[i]);
                acc[i][0] = fma2(qd, t01, acc[i][0]);
                acc[i][1] = fma2(qd, t23, acc[i][1]);
            }
        }
        __syncthreads();
    }

    float4 dbv = *(const float4*)(g_db + b * NN + n0 + lane * 4);
    float dbx[4] = {dbv.x, dbv.y, dbv.z, dbv.w};
    #pragma unroll
    for (int i = 0; i < 8; i++) {
        int q = qg * 8 + i;
        float qb = g_qb[q];
        float a0, a1, a2, a3;
        unpack2(acc[i][0], a0, a1);
        unpack2(acc[i][1], a2, a3);
        float4 out;
        out.x = (a0 + qb) * SCALE_INV + dbx[0];
        out.y = (a1 + qb) * SCALE_INV + dbx[1];
        out.z = (a2 + qb) * SCALE_INV + dbx[2];
        out.w = (a3 + qb) * SCALE_INV + dbx[3];
        *(float4*)(g_S + ((size_t)(b * NQ + q)) * NN + n0 + lane * 4) = out;
    }
}

// ---------------- K4a: per-(b,q) logsumexp ------------------------------------
__global__ void k_logsum() {
    __shared__ float red[256];
    int row = blockIdx.x;                       // b*64+q
    const float* s = g_S + (size_t)row * NN;
    int t = threadIdx.x;
    float m = -1e30f;
    for (int i = t; i < NN; i += 256) m = fmaxf(m, s[i]);
    red[t] = m; __syncthreads();
    for (int o = 128; o > 0; o >>= 1) { if (t < o) red[t] = fmaxf(red[t], red[t + o]); __syncthreads(); }
    m = red[0]; __syncthreads();
    float sum = 0.f;
    for (int i = t; i < NN; i += 256) sum += __expf(s[i] - m);
    red[t] = sum; __syncthreads();
    for (int o = 128; o > 0; o >>= 1) { if (t < o) red[t] += red[t + o]; __syncthreads(); }
    if (t == 0) g_L[row] = m + logf(red[0]);
}

// ---------------- K4b: t[b,n] = max_q (s - L[q]) -------------------------------
__global__ void k_importance() {
    __shared__ float Ls[NQ];
    int b = blockIdx.y;
    int n = blockIdx.x * 256 + threadIdx.x;
    if (threadIdx.x < NQ) Ls[threadIdx.x] = g_L[b * NQ + threadIdx.x];
    __syncthreads();
    const float* s = g_S + (size_t)b * NQ * NN;
    float m = -1e30f;
    #pragma unroll 8
    for (int q = 0; q < NQ; q++) m = fmaxf(m, s[(size_t)q * NN + n] - Ls[q]);
    g_t[b * NN + n] = m;
}

// ---------------- K5: exact top-1024 + ascending-index compaction --------------
// one block per batch, 1024 threads; warp-shfl scans + packed-byte histograms
__global__ __launch_bounds__(1024) void k_select() {
    __shared__ unsigned key[NN];
    __shared__ int hist[16];
    __shared__ unsigned s_p;
    __shared__ int s_k;
    __shared__ int warp_g[32], warp_e[32];
    int b = blockIdx.x, t = threadIdx.x;
    int lane = t & 31, wid = t >> 5;

    for (int i = t; i < NN; i += 1024) {
        unsigned x = __float_as_uint(g_t[b * NN + i]);
        key[i] = x ^ ((unsigned)((int)x >> 31) | 0x80000000u);  // order-preserving flip
    }
    if (t == 0) { s_p = 0u; s_k = TOPK; }
    __syncthreads();

    unsigned k0 = key[t * 4], k1 = key[t * 4 + 1], k2 = key[t * 4 + 2], k3 = key[t * 4 + 3];

    // 4-bit radix select of the TOPK-th largest key
    for (int shift = 28; shift >= 0; shift -= 4) {
        if (t < 16) hist[t] = 0;
        __syncthreads();
        unsigned p = s_p;
        unsigned hm = (shift == 28) ? 0u : (0xFFFFFFFFu << (shift + 4));
        unsigned long long lo = 0ull, hi = 0ull;
        #define ACCD(kx) { if (((kx) & hm) == (p & hm)) { int dg = ((kx) >> shift) & 15; \
                            if (dg < 8) lo += 1ull << (dg * 8); else hi += 1ull << ((dg - 8) * 8); } }
        ACCD(k0) ACCD(k1) ACCD(k2) ACCD(k3)
        #undef ACCD
        #pragma unroll
        for (int o = 16; o > 0; o >>= 1) {
            lo += __shfl_down_sync(0xffffffffu, lo, o);
            hi += __shfl_down_sync(0xffffffffu, hi, o);
        }
        // broadcast the complete warp totals from lane 0 (lanes 1..7 hold partials!)
        lo = __shfl_sync(0xffffffffu, lo, 0);
        hi = __shfl_sync(0xffffffffu, hi, 0);
        if (lane < 8) {
            int c = (int)((lo >> (lane * 8)) & 0xff);
            if (c) atomicAdd(&hist[lane], c);
            int c2 = (int)((hi >> (lane * 8)) & 0xff);
            if (c2) atomicAdd(&hist[lane + 8], c2);
        }
        __syncthreads();
        if (t == 0) {
            int k = s_k, bin;
            for (bin = 15; bin > 0; bin--) {
                int c = hist[bin];
                if (k <= c) break;
                k -= c;
            }
            s_p = p | ((unsigned)bin << shift);
            s_k = k;
        }
        __syncthreads();
    }
    unsigned thr = s_p;
    int eq_need = s_k;   // # threshold-equal tokens to take (lowest indices first)

    int gl[4], el[4], gs = 0, es = 0;
    unsigned kr[4] = {k0, k1, k2, k3};
    #pragma unroll
    for (int i = 0; i < 4; i++) {
        gl[i] = kr[i] > thr; el[i] = (kr[i] == thr);
        gs += gl[i]; es += el[i];
    }
    // warp inclusive scan
    int gi = gs, ei = es;
    #pragma unroll
    for (int o = 1; o < 32; o <<= 1) {
        int vg = __shfl_up_sync(0xffffffffu, gi, o);
        int ve = __shfl_up_sync(0xffffffffu, ei, o);
        if (lane >= o) { gi += vg; ei += ve; }
    }
    if (lane == 31) { warp_g[wid] = gi; warp_e[wid] = ei; }
    __syncthreads();
    if (wid == 0) {
        int vg = warp_g[lane], ve = warp_e[lane];
        int sg = vg, se2 = ve;
        #pragma unroll
        for (int o = 1; o < 32; o <<= 1) {
            int ag = __shfl_up_sync(0xffffffffu, sg, o);
            int ae = __shfl_up_sync(0xffffffffu, se2, o);
            if (lane >= o) { sg += ag; se2 += ae; }
        }
        warp_g[lane] = sg - vg;   // exclusive warp base
        warp_e[lane] = se2 - ve;
    }
    __syncthreads();
    int exg = warp_g[wid] + (gi - gs);
    int exe = warp_e[wid] + (ei - es);
    #pragma unroll
    for (int i = 0; i < 4; i++) {
        int n = t * 4 + i;
        bool sel = gl[i] || (el[i] && exe < eq_need);
        if (sel) {
            int pos = exg + min(exe, eq_need);
            g_sel[b * TOPK + pos] = n;
        }
        exg += gl[i]; exe += el[i];
    }
}

// ---------------- K6: gather selected rows ------------------------------------
__global__ void k_gather(const float* __restrict__ tf, float* __restrict__ out) {
    int b = blockIdx.y, i = blockIdx.x;
    int row = g_sel[b * TOPK + i];
    const float4* src = (const float4*)(tf + ((size_t)b * NN + row) * DD);
    float4* dst = (float4*)(out + ((size_t)b * TOPK + i) * DD);
    dst[threadIdx.x] = src[threadIdx.x];
}

// ---------------- launch -------------------------------------------------------
extern "C" void kernel_launch(void* const* d_in, const int* in_sizes, int n_in,
                              void* d_out, int out_size) {
    const float* tf   = (const float*)d_in[0];   // token_features   [8,4096,1024]
    const float* dens = (const float*)d_in[1];   // token_densities  [8,4096]
    const float* qe   = (const float*)d_in[2];   // query_embed      [64,1024]
    const float* kw   = (const float*)d_in[3];   // key_w            [1024,1024]
    const float* kb   = (const float*)d_in[4];   // key_b            [1024]
    const float* w1   = (const float*)d_in[5];   // de_w1            [1,2048]
    const float* b1   = (const float*)d_in[6];   // de_b1            [2048]
    const float* w2   = (const float*)d_in[7];   // de_w2            [2048,1]
    const float* b2   = (const float*)d_in[8];   // de_b2            [1]
    float* out = (float*)d_out;                  // [8,1024,1024]

    k_qp_part<<<dim3(64, 8), 256>>>(qe, kw);
    k_qp_reduce<<<256, 256>>>();
    k_qb<<<64, 128>>>(qe, kb);
    k_prep<<<1, 32>>>(w1, b1, w2);
    k_density<<<128, 256>>>(dens, w1, b1, w2, b2);
    k_scores<<<dim3(32, 8), 256>>>(tf);
    k_logsum<<<BB * NQ, 256>>>();
    k_importance<<<dim3(16, 8), 256>>>();
    k_select<<<BB, 1024>>>();
    k_gather<<<dim3(TOPK, BB), 256>>>(tf, out);
}

// round 5
// speedup vs baseline: 1.3903x; 1.3903x over previous
#include <cuda_runtime.h>
#include <stdint.h>

#define BB 8
#define NN 4096
#define DD 1024
#define HH 1024
#define NQ 64
#define TOPK 1024
#define SCALE_INV 0.03125f   // 1/sqrt(1024)

// ---------------- scratch (static device globals; no allocs allowed) ----------
__device__ float g_Qp_part[8 * NQ * DD];      // split-k partials for Qp
__device__ float g_Qp[NQ * DD];               // query_embed @ key_w^T   [q][d]
__device__ float g_db[BB * NN];               // density bias per token (n-varying part)
__device__ float g_S[BB * NQ * NN];           // attention scores [b][q][n]
__device__ float g_L[BB * NQ];                // logsumexp per (b,q) row
__device__ float g_t[BB * NN];                // max_q (s - L)  (monotone importance)
__device__ int   g_sel[BB * TOPK];            // selected indices, ascending

// ---------------- f32x2 helpers ----------------------------------------------
__device__ __forceinline__ unsigned long long pack2(float a, float b) {
    unsigned long long r;
    asm("mov.b64 %0, {%1,%2};" : "=l"(r) : "f"(a), "f"(b));
    return r;
}
__device__ __forceinline__ unsigned long long fma2(unsigned long long a,
                                                   unsigned long long b,
                                                   unsigned long long c) {
    unsigned long long d;
    asm("fma.rn.f32x2 %0, %1, %2, %3;" : "=l"(d) : "l"(a), "l"(b), "l"(c));
    return d;
}
__device__ __forceinline__ void unpack2(unsigned long long v, float& lo, float& hi) {
    asm("mov.b64 {%0,%1}, %2;" : "=f"(lo), "=f"(hi) : "l"(v));
}

// ---------------- K1a: Qp split-k partials ------------------------------------
// grid (64 d-tiles of 16, 8 k-splits of 128), block 256
__global__ void k_qp_part(const float* __restrict__ qe, const float* __restrict__ kw) {
    __shared__ float qe_s[64 * 129];
    __shared__ float kw_s[16 * 129];
    int t = threadIdx.x;
    int d0 = blockIdx.x * 16;
    int k0 = blockIdx.y * 128;
    #pragma unroll
    for (int i = 0; i < 32; i++) {
        int idx = t + i * 256;
        int q = idx >> 7, k = idx & 127;
        qe_s[q * 129 + k] = qe[q * HH + k0 + k];
    }
    #pragma unroll
    for (int i = 0; i < 8; i++) {
        int idx = t + i * 256;
        int d = idx >> 7, k = idx & 127;
        kw_s[d * 129 + k] = kw[(size_t)(d0 + d) * HH + k0 + k];
    }
    __syncthreads();
    int tq = t & 63, tg = t >> 6;
    float acc[4] = {0.f, 0.f, 0.f, 0.f};
    for (int k = 0; k < 128; k++) {
        float qv = qe_s[tq * 129 + k];
        #pragma unroll
        for (int i = 0; i < 4; i++)
            acc[i] = fmaf(qv, kw_s[(tg * 4 + i) * 129 + k], acc[i]);
    }
    #pragma unroll
    for (int i = 0; i < 4; i++)
        g_Qp_part[(size_t)blockIdx.y * (NQ * DD) + tq * DD + d0 + tg * 4 + i] = acc[i];
}

// ---------------- K1b: reduce split-k ----------------------------------------
__global__ void k_qp_reduce() {
    int idx = blockIdx.x * 256 + threadIdx.x;   // 65536 total
    float s = 0.f;
    #pragma unroll
    for (int j = 0; j < 8; j++) s += g_Qp_part[(size_t)j * (NQ * DD) + idx];
    g_Qp[idx] = s;
}

// ---------------- K2: density bias (MLP collapsed analytically, fused) --------
// relu(d*w1 + b1)*w2 with b1==0 and d>=0 reduces to d*w1*w2 for w1>0.
// Each block redundantly computes C1 with an IDENTICAL deterministic reduction
// (so every token sees bit-identical C1) plus a scan-ordered irregular list
// for any b1 != 0 terms (exact general path; empty for this problem).
// Constant-over-n terms (de_b2, and key_b's qb) cancel in softmax -> dropped.
__global__ __launch_bounds__(256) void k_density(const float* __restrict__ dens,
                                                 const float* __restrict__ w1,
                                                 const float* __restrict__ b1,
                                                 const float* __restrict__ w2) {
    __shared__ float s_w1[2048], s_b1[2048], s_w2[2048];
    __shared__ float red[8];
    __shared__ int   wbase[8];
    __shared__ int   s_irr[2048];
    __shared__ int   s_m;
    __shared__ float s_C1;
    int t = threadIdx.x, lane = t & 31, wid = t >> 5;

    for (int i = t; i < 2048; i += 256) { s_w1[i] = w1[i]; s_b1[i] = b1[i]; s_w2[i] = w2[i]; }
    __syncthreads();

    // 8 contiguous j per thread -> thread-order scan yields ascending-j list
    float c = 0.f; int cnt = 0; int loc[8];
    #pragma unroll
    for (int i = 0; i < 8; i++) {
        int j = t * 8 + i;
        float a = s_w1[j], bb = s_b1[j];
        if (bb != 0.f) loc[cnt++] = j;
        else if (a > 0.f) c = fmaf(a, s_w2[j], c);
    }
    // warp inclusive scan of counts + warp reduce of c
    int inc = cnt;
    #pragma unroll
    for (int o = 1; o < 32; o <<= 1) {
        int v = __shfl_up_sync(0xffffffffu, inc, o);
        if (lane >= o) inc += v;
    }
    #pragma unroll
    for (int o = 16; o > 0; o >>= 1) c += __shfl_down_sync(0xffffffffu, c, o);
    if (lane == 31) wbase[wid] = inc;
    if (lane == 0)  red[wid] = c;
    __syncthreads();
    if (wid == 0) {
        int v = (lane < 8) ? wbase[lane] : 0;
        int sc = v;
        #pragma unroll
        for (int o = 1; o < 32; o <<= 1) {
            int a2 = __shfl_up_sync(0xffffffffu, sc, o);
            if (lane >= o) sc += a2;
        }
        if (lane < 8) wbase[lane] = sc - v;     // exclusive warp base
        if (lane == 31) s_m = sc;               // total irregular count
        float cc = (lane < 8) ? red[lane] : 0.f;
        #pragma unroll
        for (int o = 16; o > 0; o >>= 1) cc += __shfl_down_sync(0xffffffffu, cc, o);
        if (lane == 0) s_C1 = cc;
    }
    __syncthreads();
    int base = wbase[wid] + (inc - cnt);
    for (int k = 0; k < cnt; k++) s_irr[base + k] = loc[k];
    __syncthreads();

    int idx = blockIdx.x * 256 + t;             // < 32768
    float d = dens[idx];
    float acc = d * s_C1;
    int m = s_m;
    for (int i = 0; i < m; i++) {
        int j = s_irr[i];
        acc += fmaxf(fmaf(d, s_w1[j], s_b1[j]), 0.f) * s_w2[j];
    }
    g_db[idx] = acc;
}

// ---------------- K3: scores GEMM  S[b,q,n] -----------------------------------
// grid (32 n-tiles of 128, 8 b) = 256 blocks, block 256, 2 CTAs/SM -> one wave.
// Thread tile 8q x 4n via f32x2; k-chunk 32.
#define TFS 132
#define BK  32
__global__ __launch_bounds__(256, 2) void k_scores(const float* __restrict__ tf) {
    __shared__ __align__(16) float tf_s[BK * TFS];   // [kk][n], padded rows
    __shared__ __align__(16) float qp_s[BK * 64];    // [kk][q]
    int t = threadIdx.x;
    int n0 = blockIdx.x * 128;
    int b  = blockIdx.y;
    int qg = t >> 5, lane = t & 31;
    const float* tfb = tf + (size_t)b * NN * DD;

    unsigned long long acc[8][2];
    #pragma unroll
    for (int i = 0; i < 8; i++) { acc[i][0] = 0ull; acc[i][1] = 0ull; }

    for (int k0 = 0; k0 < DD; k0 += BK) {
        // tf chunk: 128 rows x 32 k -> k-major smem (1024 float4, 4 per thread)
        #pragma unroll
        for (int r = 0; r < 4; r++) {
            int f = t + r * 256;
            int n = f >> 3, kq = (f & 7) * 4;
            float4 v = *(const float4*)(tfb + (size_t)(n0 + n) * DD + k0 + kq);
            tf_s[(kq + 0) * TFS + n] = v.x;
            tf_s[(kq + 1) * TFS + n] = v.y;
            tf_s[(kq + 2) * TFS + n] = v.z;
            tf_s[(kq + 3) * TFS + n] = v.w;
        }
        // Qp chunk: 64 rows x 32 k -> k-major smem (512 float4, 2 per thread)
        #pragma unroll
        for (int r = 0; r < 2; r++) {
            int f = t + r * 256;
            int q = f >> 3, kq = (f & 7) * 4;
            float4 v = *(const float4*)(g_Qp + (size_t)q * DD + k0 + kq);
            qp_s[(kq + 0) * 64 + q] = v.x;
            qp_s[(kq + 1) * 64 + q] = v.y;
            qp_s[(kq + 2) * 64 + q] = v.z;
            qp_s[(kq + 3) * 64 + q] = v.w;
        }
        __syncthreads();
        #pragma unroll
        for (int kk = 0; kk < BK; kk++) {
            float4 tv = *(const float4*)&tf_s[kk * TFS + lane * 4];
            unsigned long long t01 = pack2(tv.x, tv.y);
            unsigned long long t23 = pack2(tv.z, tv.w);
            float4 qa = *(const float4*)&qp_s[kk * 64 + qg * 8];
            float4 qc = *(const float4*)&qp_s[kk * 64 + qg * 8 + 4];
            float qv[8] = {qa.x, qa.y, qa.z, qa.w, qc.x, qc.y, qc.z, qc.w};
            #pragma unroll
            for (int i = 0; i < 8; i++) {
                unsigned long long qd = pack2(qv[i], qv[i]);
                acc[i][0] = fma2(qd, t01, acc[i][0]);
                acc[i][1] = fma2(qd, t23, acc[i][1]);
            }
        }
        __syncthreads();
    }

    float4 dbv = *(const float4*)(g_db + b * NN + n0 + lane * 4);
    float dbx[4] = {dbv.x, dbv.y, dbv.z, dbv.w};
    #pragma unroll
    for (int i = 0; i < 8; i++) {
        int q = qg * 8 + i;
        float a0, a1, a2, a3;
        unpack2(acc[i][0], a0, a1);
        unpack2(acc[i][1], a2, a3);
        float4 out;
        out.x = a0 * SCALE_INV + dbx[0];
        out.y = a1 * SCALE_INV + dbx[1];
        out.z = a2 * SCALE_INV + dbx[2];
        out.w = a3 * SCALE_INV + dbx[3];
        *(float4*)(g_S + ((size_t)(b * NQ + q)) * NN + n0 + lane * 4) = out;
    }
}

// ---------------- K4a: per-(b,q) logsumexp ------------------------------------
__global__ void k_logsum() {
    __shared__ float red[256];
    int row = blockIdx.x;                       // b*64+q
    const float* s = g_S + (size_t)row * NN;
    int t = threadIdx.x;
    float m = -1e30f;
    for (int i = t; i < NN; i += 256) m = fmaxf(m, s[i]);
    red[t] = m; __syncthreads();
    for (int o = 128; o > 0; o >>= 1) { if (t < o) red[t] = fmaxf(red[t], red[t + o]); __syncthreads(); }
    m = red[0]; __syncthreads();
    float sum = 0.f;
    for (int i = t; i < NN; i += 256) sum += __expf(s[i] - m);
    red[t] = sum; __syncthreads();
    for (int o = 128; o > 0; o >>= 1) { if (t < o) red[t] += red[t + o]; __syncthreads(); }
    if (t == 0) g_L[row] = m + logf(red[0]);
}

// ---------------- K4b: t[b,n] = max_q (s - L[q]) -------------------------------
__global__ void k_importance() {
    __shared__ float Ls[NQ];
    int b = blockIdx.y;
    int n = blockIdx.x * 256 + threadIdx.x;
    if (threadIdx.x < NQ) Ls[threadIdx.x] = g_L[b * NQ + threadIdx.x];
    __syncthreads();
    const float* s = g_S + (size_t)b * NQ * NN;
    float m = -1e30f;
    #pragma unroll 8
    for (int q = 0; q < NQ; q++) m = fmaxf(m, s[(size_t)q * NN + n] - Ls[q]);
    g_t[b * NN + n] = m;
}

// ---------------- K5: exact top-1024 + ascending-index compaction --------------
// one block per batch, 1024 threads; warp-shfl scans + packed-byte histograms
__global__ __launch_bounds__(1024) void k_select() {
    __shared__ unsigned key[NN];
    __shared__ int hist[16];
    __shared__ unsigned s_p;
    __shared__ int s_k;
    __shared__ int warp_g[32], warp_e[32];
    int b = blockIdx.x, t = threadIdx.x;
    int lane = t & 31, wid = t >> 5;

    for (int i = t; i < NN; i += 1024) {
        unsigned x = __float_as_uint(g_t[b * NN + i]);
        key[i] = x ^ ((unsigned)((int)x >> 31) | 0x80000000u);  // order-preserving flip
    }
    if (t == 0) { s_p = 0u; s_k = TOPK; }
    __syncthreads();

    unsigned k0 = key[t * 4], k1 = key[t * 4 + 1], k2 = key[t * 4 + 2], k3 = key[t * 4 + 3];

    // 4-bit radix select of the TOPK-th largest key
    for (int shift = 28; shift >= 0; shift -= 4) {
        if (t < 16) hist[t] = 0;
        __syncthreads();
        unsigned p = s_p;
        unsigned hm = (shift == 28) ? 0u : (0xFFFFFFFFu << (shift + 4));
        unsigned long long lo = 0ull, hi = 0ull;
        #define ACCD(kx) { if (((kx) & hm) == (p & hm)) { int dg = ((kx) >> shift) & 15; \
                            if (dg < 8) lo += 1ull << (dg * 8); else hi += 1ull << ((dg - 8) * 8); } }
        ACCD(k0) ACCD(k1) ACCD(k2) ACCD(k3)
        #undef ACCD
        #pragma unroll
        for (int o = 16; o > 0; o >>= 1) {
            lo += __shfl_down_sync(0xffffffffu, lo, o);
            hi += __shfl_down_sync(0xffffffffu, hi, o);
        }
        // broadcast complete warp totals from lane 0 (other lanes hold partials)
        lo = __shfl_sync(0xffffffffu, lo, 0);
        hi = __shfl_sync(0xffffffffu, hi, 0);
        if (lane < 8) {
            int c = (int)((lo >> (lane * 8)) & 0xff);
            if (c) atomicAdd(&hist[lane], c);
            int c2 = (int)((hi >> (lane * 8)) & 0xff);
            if (c2) atomicAdd(&hist[lane + 8], c2);
        }
        __syncthreads();
        if (t == 0) {
            int k = s_k, bin;
            for (bin = 15; bin > 0; bin--) {
                int c = hist[bin];
                if (k <= c) break;
                k -= c;
            }
            s_p = p | ((unsigned)bin << shift);
            s_k = k;
        }
        __syncthreads();
    }
    unsigned thr = s_p;
    int eq_need = s_k;   // # threshold-equal tokens to take (lowest indices first)

    int gl[4], el[4], gs = 0, es = 0;
    unsigned kr[4] = {k0, k1, k2, k3};
    #pragma unroll
    for (int i = 0; i < 4; i++) {
        gl[i] = kr[i] > thr; el[i] = (kr[i] == thr);
        gs += gl[i]; es += el[i];
    }
    // warp inclusive scan
    int gi = gs, ei = es;
    #pragma unroll
    for (int o = 1; o < 32; o <<= 1) {
        int vg = __shfl_up_sync(0xffffffffu, gi, o);
        int ve = __shfl_up_sync(0xffffffffu, ei, o);
        if (lane >= o) { gi += vg; ei += ve; }
    }
    if (lane == 31) { warp_g[wid] = gi; warp_e[wid] = ei; }
    __syncthreads();
    if (wid == 0) {
        int vg = warp_g[lane], ve = warp_e[lane];
        int sg = vg, se2 = ve;
        #pragma unroll
        for (int o = 1; o < 32; o <<= 1) {
            int ag = __shfl_up_sync(0xffffffffu, sg, o);
            int ae = __shfl_up_sync(0xffffffffu, se2, o);
            if (lane >= o) { sg += ag; se2 += ae; }
        }
        warp_g[lane] = sg - vg;   // exclusive warp base
        warp_e[lane] = se2 - ve;
    }
    __syncthreads();
    int exg = warp_g[wid] + (gi - gs);
    int exe = warp_e[wid] + (ei - es);
    #pragma unroll
    for (int i = 0; i < 4; i++) {
        int n = t * 4 + i;
        bool sel = gl[i] || (el[i] && exe < eq_need);
        if (sel) {
            int pos = exg + min(exe, eq_need);
            g_sel[b * TOPK + pos] = n;
        }
        exg += gl[i]; exe += el[i];
    }
}

// ---------------- K6: gather selected rows ------------------------------------
__global__ void k_gather(const float* __restrict__ tf, float* __restrict__ out) {
    int b = blockIdx.y, i = blockIdx.x;
    int row = g_sel[b * TOPK + i];
    const float4* src = (const float4*)(tf + ((size_t)b * NN + row) * DD);
    float4* dst = (float4*)(out + ((size_t)b * TOPK + i) * DD);
    dst[threadIdx.x] = src[threadIdx.x];
}

// ---------------- launch -------------------------------------------------------
extern "C" void kernel_launch(void* const* d_in, const int* in_sizes, int n_in,
                              void* d_out, int out_size) {
    const float* tf   = (const float*)d_in[0];   // token_features   [8,4096,1024]
    const float* dens = (const float*)d_in[1];   // token_densities  [8,4096]
    const float* qe   = (const float*)d_in[2];   // query_embed      [64,1024]
    const float* kw   = (const float*)d_in[3];   // key_w            [1024,1024]
    const float* w1   = (const float*)d_in[5];   // de_w1            [1,2048]
    const float* b1   = (const float*)d_in[6];   // de_b1            [2048]
    const float* w2   = (const float*)d_in[7];   // de_w2            [2048,1]
    float* out = (float*)d_out;                  // [8,1024,1024]

    k_qp_part<<<dim3(64, 8), 256>>>(qe, kw);
    k_qp_reduce<<<256, 256>>>();
    k_density<<<128, 256>>>(dens, w1, b1, w2);
    k_scores<<<dim3(32, 8), 256>>>(tf);
    k_logsum<<<BB * NQ, 256>>>();
    k_importance<<<dim3(16, 8), 256>>>();
    k_select<<<BB, 1024>>>();
    k_gather<<<dim3(TOPK, BB), 256>>>(tf, out);
}

// round 7
// speedup vs baseline: 1.4879x; 1.0703x over previous
#include <cuda_runtime.h>
#include <stdint.h>

#define BB 8
#define NN 4096
#define DD 1024
#define HH 1024
#define NQ 64
#define TOPK 1024
#define SCALE_INV 0.03125f   // 1/sqrt(1024)

// ---------------- scratch (static device globals; no allocs allowed) ----------
__device__ float g_Qp_part[8 * NQ * DD];      // split-k partials for Qp
__device__ float g_Qp[NQ * DD];               // query_embed @ key_w^T   [q][d]
__device__ float g_db[BB * NN];               // density bias per token (n-varying part)
__device__ float g_S[BB * NQ * NN];           // attention scores [b][q][n]
__device__ float g_L[BB * NQ];                // logsumexp per (b,q) row
__device__ float g_t[BB * NN];                // max_q (s - L)  (monotone importance)
__device__ int   g_sel[BB * TOPK];            // selected indices, ascending

// ---------------- f32x2 helpers ----------------------------------------------
__device__ __forceinline__ unsigned long long pack2(float a, float b) {
    unsigned long long r;
    asm("mov.b64 %0, {%1,%2};" : "=l"(r) : "f"(a), "f"(b));
    return r;
}
__device__ __forceinline__ unsigned long long fma2(unsigned long long a,
                                                   unsigned long long b,
                                                   unsigned long long c) {
    unsigned long long d;
    asm("fma.rn.f32x2 %0, %1, %2, %3;" : "=l"(d) : "l"(a), "l"(b), "l"(c));
    return d;
}
__device__ __forceinline__ void unpack2(unsigned long long v, float& lo, float& hi) {
    asm("mov.b64 {%0,%1}, %2;" : "=f"(lo), "=f"(hi) : "l"(v));
}

// ---------------- K1a: Qp split-k partials ------------------------------------
// grid (64 d-tiles of 16, 8 k-splits of 128), block 256
__global__ void k_qp_part(const float* __restrict__ qe, const float* __restrict__ kw) {
    __shared__ float qe_s[64 * 129];
    __shared__ float kw_s[16 * 129];
    int t = threadIdx.x;
    int d0 = blockIdx.x * 16;
    int k0 = blockIdx.y * 128;
    #pragma unroll
    for (int i = 0; i < 32; i++) {
        int idx = t + i * 256;
        int q = idx >> 7, k = idx & 127;
        qe_s[q * 129 + k] = qe[q * HH + k0 + k];
    }
    #pragma unroll
    for (int i = 0; i < 8; i++) {
        int idx = t + i * 256;
        int d = idx >> 7, k = idx & 127;
        kw_s[d * 129 + k] = kw[(size_t)(d0 + d) * HH + k0 + k];
    }
    __syncthreads();
    int tq = t & 63, tg = t >> 6;
    float acc[4] = {0.f, 0.f, 0.f, 0.f};
    for (int k = 0; k < 128; k++) {
        float qv = qe_s[tq * 129 + k];
        #pragma unroll
        for (int i = 0; i < 4; i++)
            acc[i] = fmaf(qv, kw_s[(tg * 4 + i) * 129 + k], acc[i]);
    }
    #pragma unroll
    for (int i = 0; i < 4; i++)
        g_Qp_part[(size_t)blockIdx.y * (NQ * DD) + tq * DD + d0 + tg * 4 + i] = acc[i];
}

// ---------------- K1b: reduce split-k ----------------------------------------
__global__ void k_qp_reduce() {
    int idx = blockIdx.x * 256 + threadIdx.x;   // 65536 total
    float s = 0.f;
    #pragma unroll
    for (int j = 0; j < 8; j++) s += g_Qp_part[(size_t)j * (NQ * DD) + idx];
    g_Qp[idx] = s;
}

// ---------------- K2: density bias (MLP collapsed analytically, fused) --------
__global__ __launch_bounds__(256) void k_density(const float* __restrict__ dens,
                                                 const float* __restrict__ w1,
                                                 const float* __restrict__ b1,
                                                 const float* __restrict__ w2) {
    __shared__ float s_w1[2048], s_b1[2048], s_w2[2048];
    __shared__ float red[8];
    __shared__ int   wbase[8];
    __shared__ int   s_irr[2048];
    __shared__ int   s_m;
    __shared__ float s_C1;
    int t = threadIdx.x, lane = t & 31, wid = t >> 5;

    for (int i = t; i < 2048; i += 256) { s_w1[i] = w1[i]; s_b1[i] = b1[i]; s_w2[i] = w2[i]; }
    __syncthreads();

    float c = 0.f; int cnt = 0; int loc[8];
    #pragma unroll
    for (int i = 0; i < 8; i++) {
        int j = t * 8 + i;
        float a = s_w1[j], bb = s_b1[j];
        if (bb != 0.f) loc[cnt++] = j;
        else if (a > 0.f) c = fmaf(a, s_w2[j], c);
    }
    int inc = cnt;
    #pragma unroll
    for (int o = 1; o < 32; o <<= 1) {
        int v = __shfl_up_sync(0xffffffffu, inc, o);
        if (lane >= o) inc += v;
    }
    #pragma unroll
    for (int o = 16; o > 0; o >>= 1) c += __shfl_down_sync(0xffffffffu, c, o);
    if (lane == 31) wbase[wid] = inc;
    if (lane == 0)  red[wid] = c;
    __syncthreads();
    if (wid == 0) {
        int v = (lane < 8) ? wbase[lane] : 0;
        int sc = v;
        #pragma unroll
        for (int o = 1; o < 32; o <<= 1) {
            int a2 = __shfl_up_sync(0xffffffffu, sc, o);
            if (lane >= o) sc += a2;
        }
        if (lane < 8) wbase[lane] = sc - v;
        if (lane == 31) s_m = sc;
        float cc = (lane < 8) ? red[lane] : 0.f;
        #pragma unroll
        for (int o = 16; o > 0; o >>= 1) cc += __shfl_down_sync(0xffffffffu, cc, o);
        if (lane == 0) s_C1 = cc;
    }
    __syncthreads();
    int base = wbase[wid] + (inc - cnt);
    for (int k = 0; k < cnt; k++) s_irr[base + k] = loc[k];
    __syncthreads();

    int idx = blockIdx.x * 256 + t;
    float d = dens[idx];
    float acc = d * s_C1;
    int m = s_m;
    for (int i = 0; i < m; i++) {
        int j = s_irr[i];
        acc += fmaxf(fmaf(d, s_w1[j], s_b1[j]), 0.f) * s_w2[j];
    }
    g_db[idx] = acc;
}

// ---------------- K3: scores GEMM  S[b,q,n] -----------------------------------
// grid (32 n-tiles of 128, 8 b) = 256 blocks, block 256, 2 CTAs/SM -> one wave.
// Double-buffered smem software pipeline (BK=16); q-paired f32x2 accumulators.
#define TFS 132
#define BK  16
#define NCHUNK (DD / BK)
__global__ __launch_bounds__(256, 2) void k_scores(const float* __restrict__ tf) {
    __shared__ __align__(16) float tf_s[2][BK * TFS];   // [buf][kk][n]
    __shared__ __align__(16) float qp_s[2][BK * 64];    // [buf][kk][q]
    int t = threadIdx.x;
    int n0 = blockIdx.x * 128;
    int b  = blockIdx.y;
    int qg = t >> 5, lane = t & 31;
    const float* tfb = tf + (size_t)b * NN * DD;

    // prefetch addressing: per chunk each thread moves 3 float4
    int tn = t >> 2;             // tf rows tn and tn+64
    int tk = (t & 3) * 4;        // k-quad within chunk
    const float* tf_src0 = tfb + (size_t)(n0 + tn) * DD + tk;
    const float* tf_src1 = tfb + (size_t)(n0 + tn + 64) * DD + tk;
    const float* qp_src  = g_Qp + (size_t)tn * DD + tk;   // tn<64 rows only? no: tn in 0..63? t>>2 in 0..63 -> yes

    float4 ptf0, ptf1, pqp;

    // chunk 0 loads
    ptf0 = *(const float4*)(tf_src0);
    ptf1 = *(const float4*)(tf_src1);
    pqp  = *(const float4*)(qp_src);
    // store chunk 0 -> buf 0
    {
        tf_s[0][(tk + 0) * TFS + tn] = ptf0.x;
        tf_s[0][(tk + 1) * TFS + tn] = ptf0.y;
        tf_s[0][(tk + 2) * TFS + tn] = ptf0.z;
        tf_s[0][(tk + 3) * TFS + tn] = ptf0.w;
        tf_s[0][(tk + 0) * TFS + tn + 64] = ptf1.x;
        tf_s[0][(tk + 1) * TFS + tn + 64] = ptf1.y;
        tf_s[0][(tk + 2) * TFS + tn + 64] = ptf1.z;
        tf_s[0][(tk + 3) * TFS + tn + 64] = ptf1.w;
        qp_s[0][(tk + 0) * 64 + tn] = pqp.x;
        qp_s[0][(tk + 1) * 64 + tn] = pqp.y;
        qp_s[0][(tk + 2) * 64 + tn] = pqp.z;
        qp_s[0][(tk + 3) * 64 + tn] = pqp.w;
    }
    // prefetch chunk 1 into regs
    ptf0 = *(const float4*)(tf_src0 + BK);
    ptf1 = *(const float4*)(tf_src1 + BK);
    pqp  = *(const float4*)(qp_src  + BK);

    unsigned long long acc[4][4];   // [q-pair][n], pair over (q_even, q_odd)
    #pragma unroll
    for (int i = 0; i < 4; i++)
        #pragma unroll
        for (int j = 0; j < 4; j++) acc[i][j] = 0ull;

    for (int c = 0; c < NCHUNK; c++) {
        __syncthreads();   // buf[c&1] ready; all reads of buf[(c+1)&1] (chunk c-1) done
        if (c + 1 < NCHUNK) {
            int nb = (c + 1) & 1;
            tf_s[nb][(tk + 0) * TFS + tn] = ptf0.x;
            tf_s[nb][(tk + 1) * TFS + tn] = ptf0.y;
            tf_s[nb][(tk + 2) * TFS + tn] = ptf0.z;
            tf_s[nb][(tk + 3) * TFS + tn] = ptf0.w;
            tf_s[nb][(tk + 0) * TFS + tn + 64] = ptf1.x;
            tf_s[nb][(tk + 1) * TFS + tn + 64] = ptf1.y;
            tf_s[nb][(tk + 2) * TFS + tn + 64] = ptf1.z;
            tf_s[nb][(tk + 3) * TFS + tn + 64] = ptf1.w;
            qp_s[nb][(tk + 0) * 64 + tn] = pqp.x;
            qp_s[nb][(tk + 1) * 64 + tn] = pqp.y;
            qp_s[nb][(tk + 2) * 64 + tn] = pqp.z;
            qp_s[nb][(tk + 3) * 64 + tn] = pqp.w;
        }
        if (c + 2 < NCHUNK) {
            int ko = (c + 2) * BK;
            ptf0 = *(const float4*)(tf_src0 + ko);
            ptf1 = *(const float4*)(tf_src1 + ko);
            pqp  = *(const float4*)(qp_src  + ko);
        }
        int cb = c & 1;
        #pragma unroll
        for (int kk = 0; kk < BK; kk++) {
            float4 tv = *(const float4*)&tf_s[cb][kk * TFS + lane * 4];
            ulonglong2 qlo = *(const ulonglong2*)&qp_s[cb][kk * 64 + qg * 8];
            ulonglong2 qhi = *(const ulonglong2*)&qp_s[cb][kk * 64 + qg * 8 + 4];
            float tn4[4] = {tv.x, tv.y, tv.z, tv.w};
            #pragma unroll
            for (int n = 0; n < 4; n++) {
                unsigned long long bb2 = pack2(tn4[n], tn4[n]);
                acc[0][n] = fma2(qlo.x, bb2, acc[0][n]);
                acc[1][n] = fma2(qlo.y, bb2, acc[1][n]);
                acc[2][n] = fma2(qhi.x, bb2, acc[2][n]);
                acc[3][n] = fma2(qhi.y, bb2, acc[3][n]);
            }
        }
    }

    float4 dbv = *(const float4*)(g_db + b * NN + n0 + lane * 4);
    float dbx[4] = {dbv.x, dbv.y, dbv.z, dbv.w};
    #pragma unroll
    for (int qp = 0; qp < 4; qp++) {
        float e[4], o[4];
        #pragma unroll
        for (int n = 0; n < 4; n++) unpack2(acc[qp][n], e[n], o[n]);
        int q0 = qg * 8 + qp * 2;
        float4 out0, out1;
        out0.x = e[0] * SCALE_INV + dbx[0];
        out0.y = e[1] * SCALE_INV + dbx[1];
        out0.z = e[2] * SCALE_INV + dbx[2];
        out0.w = e[3] * SCALE_INV + dbx[3];
        out1.x = o[0] * SCALE_INV + dbx[0];
        out1.y = o[1] * SCALE_INV + dbx[1];
        out1.z = o[2] * SCALE_INV + dbx[2];
        out1.w = o[3] * SCALE_INV + dbx[3];
        *(float4*)(g_S + ((size_t)(b * NQ + q0)) * NN + n0 + lane * 4)     = out0;
        *(float4*)(g_S + ((size_t)(b * NQ + q0 + 1)) * NN + n0 + lane * 4) = out1;
    }
}

// ---------------- K4a: per-(b,q) logsumexp ------------------------------------
__global__ void k_logsum() {
    __shared__ float red[256];
    int row = blockIdx.x;                       // b*64+q
    const float* s = g_S + (size_t)row * NN;
    int t = threadIdx.x;
    float m = -1e30f;
    for (int i = t; i < NN; i += 256) m = fmaxf(m, s[i]);
    red[t] = m; __syncthreads();
    for (int o = 128; o > 0; o >>= 1) { if (t < o) red[t] = fmaxf(red[t], red[t + o]); __syncthreads(); }
    m = red[0]; __syncthreads();
    float sum = 0.f;
    for (int i = t; i < NN; i += 256) sum += __expf(s[i] - m);
    red[t] = sum; __syncthreads();
    for (int o = 128; o > 0; o >>= 1) { if (t < o) red[t] += red[t + o]; __syncthreads(); }
    if (t == 0) g_L[row] = m + logf(red[0]);
}

// ---------------- K4b: t[b,n] = max_q (s - L[q]) -------------------------------
__global__ void k_importance() {
    __shared__ float Ls[NQ];
    int b = blockIdx.y;
    int n = blockIdx.x * 256 + threadIdx.x;
    if (threadIdx.x < NQ) Ls[threadIdx.x] = g_L[b * NQ + threadIdx.x];
    __syncthreads();
    const float* s = g_S + (size_t)b * NQ * NN;
    float m = -1e30f;
    #pragma unroll 8
    for (int q = 0; q < NQ; q++) m = fmaxf(m, s[(size_t)q * NN + n] - Ls[q]);
    g_t[b * NN + n] = m;
}

// ---------------- K5: exact top-1024 + ascending-index compaction --------------
__global__ __launch_bounds__(1024) void k_select() {
    __shared__ unsigned key[NN];
    __shared__ int hist[16];
    __shared__ unsigned s_p;
    __shared__ int s_k;
    __shared__ int warp_g[32], warp_e[32];
    int b = blockIdx.x, t = threadIdx.x;
    int lane = t & 31, wid = t >> 5;

    for (int i = t; i < NN; i += 1024) {
        unsigned x = __float_as_uint(g_t[b * NN + i]);
        key[i] = x ^ ((unsigned)((int)x >> 31) | 0x80000000u);
    }
    if (t == 0) { s_p = 0u; s_k = TOPK; }
    __syncthreads();

    unsigned k0 = key[t * 4], k1 = key[t * 4 + 1], k2 = key[t * 4 + 2], k3 = key[t * 4 + 3];

    for (int shift = 28; shift >= 0; shift -= 4) {
        if (t < 16) hist[t] = 0;
        __syncthreads();
        unsigned p = s_p;
        unsigned hm = (shift == 28) ? 0u : (0xFFFFFFFFu << (shift + 4));
        unsigned long long lo = 0ull, hi = 0ull;
        #define ACCD(kx) { if (((kx) & hm) == (p & hm)) { int dg = ((kx) >> shift) & 15; \
                            if (dg < 8) lo += 1ull << (dg * 8); else hi += 1ull << ((dg - 8) * 8); } }
        ACCD(k0) ACCD(k1) ACCD(k2) ACCD(k3)
        #undef ACCD
        #pragma unroll
        for (int o = 16; o > 0; o >>= 1) {
            lo += __shfl_down_sync(0xffffffffu, lo, o);
            hi += __shfl_down_sync(0xffffffffu, hi, o);
        }
        lo = __shfl_sync(0xffffffffu, lo, 0);
        hi = __shfl_sync(0xffffffffu, hi, 0);
        if (lane < 8) {
            int c = (int)((lo >> (lane * 8)) & 0xff);
            if (c) atomicAdd(&hist[lane], c);
            int c2 = (int)((hi >> (lane * 8)) & 0xff);
            if (c2) atomicAdd(&hist[lane + 8], c2);
        }
        __syncthreads();
        if (t == 0) {
            int k = s_k, bin;
            for (bin = 15; bin > 0; bin--) {
                int c = hist[bin];
                if (k <= c) break;
                k -= c;
            }
            s_p = p | ((unsigned)bin << shift);
            s_k = k;
        }
        __syncthreads();
    }
    unsigned thr = s_p;
    int eq_need = s_k;

    int gl[4], el[4], gs = 0, es = 0;
    unsigned kr[4] = {k0, k1, k2, k3};
    #pragma unroll
    for (int i = 0; i < 4; i++) {
        gl[i] = kr[i] > thr; el[i] = (kr[i] == thr);
        gs += gl[i]; es += el[i];
    }
    int gi = gs, ei = es;
    #pragma unroll
    for (int o = 1; o < 32; o <<= 1) {
        int vg = __shfl_up_sync(0xffffffffu, gi, o);
        int ve = __shfl_up_sync(0xffffffffu, ei, o);
        if (lane >= o) { gi += vg; ei += ve; }
    }
    if (lane == 31) { warp_g[wid] = gi; warp_e[wid] = ei; }
    __syncthreads();
    if (wid == 0) {
        int vg = warp_g[lane], ve = warp_e[lane];
        int sg = vg, se2 = ve;
        #pragma unroll
        for (int o = 1; o < 32; o <<= 1) {
            int ag = __shfl_up_sync(0xffffffffu, sg, o);
            int ae = __shfl_up_sync(0xffffffffu, se2, o);
            if (lane >= o) { sg += ag; se2 += ae; }
        }
        warp_g[lane] = sg - vg;
        warp_e[lane] = se2 - ve;
    }
    __syncthreads();
    int exg = warp_g[wid] + (gi - gs);
    int exe = warp_e[wid] + (ei - es);
    #pragma unroll
    for (int i = 0; i < 4; i++) {
        int n = t * 4 + i;
        bool sel = gl[i] || (el[i] && exe < eq_need);
        if (sel) {
            int pos = exg + min(exe, eq_need);
            g_sel[b * TOPK + pos] = n;
        }
        exg += gl[i]; exe += el[i];
    }
}

// ---------------- K6: gather selected rows ------------------------------------
__global__ void k_gather(const float* __restrict__ tf, float* __restrict__ out) {
    int b = blockIdx.y, i = blockIdx.x;
    int row = g_sel[b * TOPK + i];
    const float4* src = (const float4*)(tf + ((size_t)b * NN + row) * DD);
    float4* dst = (float4*)(out + ((size_t)b * TOPK + i) * DD);
    dst[threadIdx.x] = src[threadIdx.x];
}

// ---------------- launch -------------------------------------------------------
extern "C" void kernel_launch(void* const* d_in, const int* in_sizes, int n_in,
                              void* d_out, int out_size) {
    const float* tf   = (const float*)d_in[0];   // token_features   [8,4096,1024]
    const float* dens = (const float*)d_in[1];   // token_densities  [8,4096]
    const float* qe   = (const float*)d_in[2];   // query_embed      [64,1024]
    const float* kw   = (const float*)d_in[3];   // key_w            [1024,1024]
    const float* w1   = (const float*)d_in[5];   // de_w1            [1,2048]
    const float* b1   = (const float*)d_in[6];   // de_b1            [2048]
    const float* w2   = (const float*)d_in[7];   // de_w2            [2048,1]
    float* out = (float*)d_out;                  // [8,1024,1024]

    k_qp_part<<<dim3(64, 8), 256>>>(qe, kw);
    k_qp_reduce<<<256, 256>>>();
    k_density<<<128, 256>>>(dens, w1, b1, w2);
    k_scores<<<dim3(32, 8), 256>>>(tf);
    k_logsum<<<BB * NQ, 256>>>();
    k_importance<<<dim3(16, 8), 256>>>();
    k_select<<<BB, 1024>>>();
    k_gather<<<dim3(TOPK, BB), 256>>>(tf, out);
}